// round 16
// baseline (speedup 1.0000x reference)
#include <cuda_runtime.h>
#include <cuda_fp16.h>
#include <math.h>
#include <stdint.h>

#define NN 50000
#define EE 800000
#define GG 512
#define HH 256
#define TT 32
#define LL 4

// ---------------- scratch (device globals) -----------------------------------
__device__ __half g_hA[NN * HH];            // residual h buffer A (fp16)
__device__ __half g_hD[NN * HH];            // residual h buffer D (fp16)
__device__ __half g_hwh[NN * HH];           // GEMM output hw' = hw*dinv (fp16)
__device__ __half g_aggh[NN * HH];          // aggregate output (fp16)
__device__ int   g_cnt[NN];
__device__ int   g_cnt2[NN];
__device__ int   g_rowptr[NN + 1];
__device__ int   g_csr[EE];                 // src BYTE offsets (src*512)
__device__ int   g_gcnt[GG];
__device__ int   g_goff[GG + 1];
__device__ float g_dinv[NN];
__device__ float g_P[100 * HH];
__device__ float g_Q[3 * HH];
__device__ float g_sums[LL * 2 * HH];
__device__ float g_pooled[GG * HH];
// fp16 hi/lo images of W^T: [L][kc=4][split=2][32768B] = 1MB
__device__ unsigned char g_Wimg[LL * 4 * 2 * 32768];

// ---------------- helpers ----------------------------------------------------
__device__ __forceinline__ uint32_t smem_u32(const void* p) {
    uint32_t a;
    asm("{ .reg .u64 t; cvta.to.shared.u64 t, %1; cvt.u32.u64 %0, t; }" : "=r"(a) : "l"(p));
    return a;
}
__device__ __forceinline__ uint32_t swz128(uint32_t o) { return o ^ ((o >> 3) & 0x70); }

__device__ __forceinline__ void ldsm4(uint32_t* r, uint32_t addr) {
    asm volatile("ldmatrix.sync.aligned.m8n8.x4.shared.b16 {%0,%1,%2,%3}, [%4];"
        : "=r"(r[0]), "=r"(r[1]), "=r"(r[2]), "=r"(r[3]) : "r"(addr));
}
__device__ __forceinline__ void mma_f16(float* d, const uint32_t* a, const uint32_t* b) {
    asm volatile("mma.sync.aligned.m16n8k16.row.col.f32.f16.f16.f32 "
        "{%0,%1,%2,%3}, {%4,%5,%6,%7}, {%8,%9}, {%0,%1,%2,%3};"
        : "+f"(d[0]), "+f"(d[1]), "+f"(d[2]), "+f"(d[3])
        : "r"(a[0]), "r"(a[1]), "r"(a[2]), "r"(a[3]), "r"(b[0]), "r"(b[1]));
}
__device__ __forceinline__ uint32_t cvt_f16x2(float lo, float hi) {
    uint32_t r;
    asm("cvt.rn.f16x2.f32 %0, %1, %2;" : "=r"(r) : "f"(hi), "f"(lo));
    return r;
}

// ---------------- fused: counting + W fp16-hi/lo images + proj tables --------
__global__ void k_count_weights(const int* __restrict__ dst, const int* __restrict__ batch,
                                int* cnt, int* gcnt,
                                const float* __restrict__ gcn_W, unsigned char* __restrict__ img,
                                const float* __restrict__ atom_emb,
                                const float* __restrict__ tag_emb,
                                const float* __restrict__ Wp, const float* __restrict__ bp,
                                float* P, float* Q) {
    int bid = blockIdx.x;
    int tid = threadIdx.x;
    if (bid < 3125) {
        int e = bid * 256 + tid;
        if (e < EE) atomicAdd(&cnt[dst[e]], 1);
        if (e < NN) atomicAdd(&gcnt[batch[e]], 1);
    } else if (bid < 3125 + 1024) {
        int idx = (bid - 3125) * 256 + tid;
        int l = idx >> 16;
        int k = (idx >> 8) & 255;
        int n = idx & 255;
        float w = gcn_W[idx];
        __half hi = __float2half(w);
        __half lo = __float2half(w - __half2float(hi));
        int kc = k >> 6, kk = k & 63;
        uint32_t off = swz128((uint32_t)(n * 128 + kk * 2));
        size_t base = ((size_t)(l * 4 + kc) * 2) * 32768;
        *(__half*)(img + base + off) = hi;
        *(__half*)(img + base + 32768 + off) = lo;
    } else {
        int r = bid - 3125 - 1024;
        int c = tid;
        if (r < 100) {
            float acc = 0.f;
            #pragma unroll 8
            for (int k = 0; k < HH; k++) acc += atom_emb[r * HH + k] * Wp[k * HH + c];
            P[r * HH + c] = acc;
        } else {
            int t = r - 100;
            if (t < 3) {
                float acc = bp[c];
                #pragma unroll
                for (int k = 0; k < TT; k++) acc += tag_emb[t * TT + k] * Wp[(HH + k) * HH + c];
                Q[t * HH + c] = acc;
            }
        }
    }
}

__global__ __launch_bounds__(1024) void k_scan(const int* __restrict__ cnt, int* rowptr,
                                               float* dinv, const int* __restrict__ gcnt,
                                               int* goff) {
    __shared__ int wsum[32];
    const int tid = threadIdx.x;
    const int lane = tid & 31;
    const int w = tid >> 5;
    const int CH = (NN + 1023) / 1024;
    const int beg = tid * CH;
    const int end = min(beg + CH, NN);

    int tot = 0;
    for (int i = beg; i < end; i++) tot += cnt[i];
    int x = tot;
    #pragma unroll
    for (int o = 1; o < 32; o <<= 1) {
        int t = __shfl_up_sync(0xFFFFFFFFu, x, o);
        if (lane >= o) x += t;
    }
    if (lane == 31) wsum[w] = x;
    __syncthreads();
    if (w == 0) {
        int y = wsum[lane];
        #pragma unroll
        for (int o = 1; o < 32; o <<= 1) {
            int t = __shfl_up_sync(0xFFFFFFFFu, y, o);
            if (lane >= o) y += t;
        }
        wsum[lane] = y;
    }
    __syncthreads();
    int run = ((w > 0) ? wsum[w - 1] : 0) + x - tot;
    if (tid == 0) rowptr[0] = 0;
    for (int i = beg; i < end; i++) {
        int cv = cnt[i];
        dinv[i] = rsqrtf((float)cv + 1.0f);
        run += cv;
        rowptr[i + 1] = run;
    }
    __syncthreads();
    int vv = (tid < GG) ? gcnt[tid] : 0;
    int xg = vv;
    #pragma unroll
    for (int o = 1; o < 32; o <<= 1) {
        int t = __shfl_up_sync(0xFFFFFFFFu, xg, o);
        if (lane >= o) xg += t;
    }
    if (lane == 31) wsum[w] = xg;
    __syncthreads();
    if (w == 0) {
        int y = wsum[lane];
        #pragma unroll
        for (int o = 1; o < 32; o <<= 1) {
            int t = __shfl_up_sync(0xFFFFFFFFu, y, o);
            if (lane >= o) y += t;
        }
        wsum[lane] = y;
    }
    __syncthreads();
    int incl = ((w > 0) ? wsum[w - 1] : 0) + xg;
    if (tid == 0) goff[0] = 0;
    if (tid < GG) goff[tid + 1] = incl;
}

// ---------------- HMMA fp16 GEMM (A single fp16, W hi/lo fp16) ---------------
#define SM_A  0
#define SM_BH 16384
#define SM_BL 32768
#define SM_GEMM 49152
#define GY_GEMM 391

__global__ __launch_bounds__(256, 2) void k_gemm_mma(
    const __half* __restrict__ aggA, const __half* __restrict__ hres,
    const float* __restrict__ sums, const float* __restrict__ bn_g,
    const float* __restrict__ bn_b,
    const unsigned char* __restrict__ WimgL,
    __half* __restrict__ C, int M,
    const float* __restrict__ P, const float* __restrict__ Q,
    const int* __restrict__ x, const int* __restrict__ tags,
    int mode, __half* __restrict__ Aout,
    const int* __restrict__ esrc, const int* __restrict__ edst,
    const int* __restrict__ rowptr, const float* __restrict__ dinv,
    int* cnt2, int* csr) {
    extern __shared__ char smem[];
    const int tid = threadIdx.x;

    if (blockIdx.y >= GY_GEMM) {                 // fused fill_csr blocks
        int e = ((blockIdx.y - GY_GEMM) * 2 + blockIdx.x) * 256 + tid;
        if (e < EE) {
            int s = esrc[e], d = edst[e];
            int pos = rowptr[d] + atomicAdd(&cnt2[d], 1);
            csr[pos] = s * (HH * 2);             // byte offset of row
        }
        return;
    }

    const int wid = tid >> 5;
    const int lane = tid & 31;
    const int wm = wid & 3;
    const int wn = wid >> 2;
    const uint32_t sb = smem_u32(smem);
    const int bm = blockIdx.y * 128;
    const int bn = blockIdx.x * 128;
    const int c4 = (tid & 15) << 2;
    const bool do_write_a = (blockIdx.x == 0);

    float acc[2][8][4];
    #pragma unroll
    for (int mi = 0; mi < 2; mi++)
        #pragma unroll
        for (int j = 0; j < 8; j++)
            #pragma unroll
            for (int q = 0; q < 4; q++) acc[mi][j][q] = 0.f;

    const float inv_n = 1.0f / (float)NN;

    for (int kc = 0; kc < 4; kc++) {
        const int col = kc * 64 + c4;
        float mu0 = 0.f, mu1 = 0.f, mu2 = 0.f, mu3 = 0.f;
        float rg0 = 0.f, rg1 = 0.f, rg2 = 0.f, rg3 = 0.f;
        float bb0 = 0.f, bb1 = 0.f, bb2 = 0.f, bb3 = 0.f;
        if (mode == 2) {
            mu0 = sums[col + 0] * inv_n;
            mu1 = sums[col + 1] * inv_n;
            mu2 = sums[col + 2] * inv_n;
            mu3 = sums[col + 3] * inv_n;
            float v0 = sums[HH + col + 0] * inv_n - mu0 * mu0;
            float v1 = sums[HH + col + 1] * inv_n - mu1 * mu1;
            float v2 = sums[HH + col + 2] * inv_n - mu2 * mu2;
            float v3 = sums[HH + col + 3] * inv_n - mu3 * mu3;
            rg0 = rsqrtf(v0 + 1e-5f) * bn_g[col + 0];
            rg1 = rsqrtf(v1 + 1e-5f) * bn_g[col + 1];
            rg2 = rsqrtf(v2 + 1e-5f) * bn_g[col + 2];
            rg3 = rsqrtf(v3 + 1e-5f) * bn_g[col + 3];
            bb0 = bn_b[col + 0];
            bb1 = bn_b[col + 1];
            bb2 = bn_b[col + 2];
            bb3 = bn_b[col + 3];
        }
        #pragma unroll
        for (int i = 0; i < 8; i++) {
            int r = (tid >> 4) + i * 16;
            int gr = bm + r;
            float4 v = make_float4(0.f, 0.f, 0.f, 0.f);
            if (gr < M) {
                if (mode == 1) {
                    int xi = x[gr], tg = tags[gr];
                    float4 p = *(const float4*)(P + (size_t)xi * HH + col);
                    float4 q = *(const float4*)(Q + (size_t)tg * HH + col);
                    v = make_float4(p.x + q.x, p.y + q.y, p.z + q.z, p.w + q.w);
                } else {
                    uint2 au = *(const uint2*)(aggA + (size_t)gr * HH + col);
                    uint2 ru = *(const uint2*)(hres + (size_t)gr * HH + col);
                    float2 a01 = __half22float2(*(const __half2*)&au.x);
                    float2 a23 = __half22float2(*(const __half2*)&au.y);
                    float2 r01 = __half22float2(*(const __half2*)&ru.x);
                    float2 r23 = __half22float2(*(const __half2*)&ru.y);
                    v.x = fmaxf((a01.x - mu0) * rg0 + bb0, 0.f) + r01.x;
                    v.y = fmaxf((a01.y - mu1) * rg1 + bb1, 0.f) + r01.y;
                    v.z = fmaxf((a23.x - mu2) * rg2 + bb2, 0.f) + r23.x;
                    v.w = fmaxf((a23.y - mu3) * rg3 + bb3, 0.f) + r23.y;
                }
            }
            uint2 hv = make_uint2(cvt_f16x2(v.x, v.y), cvt_f16x2(v.z, v.w));
            if (gr < M && do_write_a)
                *(uint2*)(Aout + (size_t)gr * HH + col) = hv;
            uint32_t off = swz128((uint32_t)(r * 128 + c4 * 2));
            *(uint2*)(smem + SM_A + off) = hv;
        }
        {
            const uint4* srcH = (const uint4*)(WimgL + (size_t)kc * 65536 + (size_t)bn * 128);
            const uint4* srcL = (const uint4*)(WimgL + (size_t)kc * 65536 + 32768 + (size_t)bn * 128);
            uint4* dstH = (uint4*)(smem + SM_BH);
            uint4* dstL = (uint4*)(smem + SM_BL);
            #pragma unroll
            for (int i = 0; i < 4; i++) {
                dstH[tid + i * 256] = srcH[tid + i * 256];
                dstL[tid + i * 256] = srcL[tid + i * 256];
            }
        }
        __syncthreads();

        #pragma unroll
        for (int ks = 0; ks < 4; ks++) {
            uint32_t ah[2][4];
            {
                int rowa = 32 * wm + (lane & 15);
                int kb = ks * 32 + ((lane >> 4) << 4);
                uint32_t off0 = swz128((uint32_t)(rowa * 128 + kb));
                uint32_t off1 = swz128((uint32_t)((rowa + 16) * 128 + kb));
                ldsm4(ah[0], sb + SM_A + off0);
                ldsm4(ah[1], sb + SM_A + off1);
            }
            #pragma unroll
            for (int jp = 0; jp < 4; jp++) {
                int n0 = 64 * wn + 16 * jp;
                int nrow = n0 + ((lane >> 4) << 3) + (lane & 7);
                int kb2 = ks * 32 + (((lane >> 3) & 1) << 4);
                uint32_t offb = swz128((uint32_t)(nrow * 128 + kb2));
                uint32_t bh[4], bl[4];
                ldsm4(bh, sb + SM_BH + offb);
                ldsm4(bl, sb + SM_BL + offb);
                #pragma unroll
                for (int mi = 0; mi < 2; mi++) {
                    #pragma unroll
                    for (int jq = 0; jq < 2; jq++) {
                        float* d = acc[mi][jp * 2 + jq];
                        mma_f16(d, ah[mi], bh + 2 * jq);
                        mma_f16(d, ah[mi], bl + 2 * jq);
                    }
                }
            }
        }
        __syncthreads();
    }

    // epilogue: fold dinv[row] into C (hw' = hw * dinv)
    #pragma unroll
    for (int mi = 0; mi < 2; mi++) {
        int r0 = bm + 32 * wm + 16 * mi + (lane >> 2);
        int r1 = r0 + 8;
        float di0 = (r0 < M) ? dinv[r0] : 0.f;
        float di1 = (r1 < M) ? dinv[r1] : 0.f;
        #pragma unroll
        for (int j = 0; j < 8; j++) {
            int c = bn + 64 * wn + 8 * j + (lane & 3) * 2;
            if (r0 < M)
                *(__half2*)(C + (size_t)r0 * HH + c) =
                    __floats2half2_rn(acc[mi][j][0] * di0, acc[mi][j][1] * di0);
            if (r1 < M)
                *(__half2*)(C + (size_t)r1 * HH + c) =
                    __floats2half2_rn(acc[mi][j][2] * di1, acc[mi][j][3] * di1);
        }
    }
}

// ---------------- aggregation: 128 thr/node, byte-offset CSR, HADD2 tree -----
// agg[v] = dinv[v]*(sum_src hw'[src] + hw'[v]) + bias,  hw' = hw*dinv prefolded.
__global__ __launch_bounds__(128) void k_aggregate(
    const __half* __restrict__ hw, const float* __restrict__ dinv,
    const int* __restrict__ rowptr, const int* __restrict__ csr,
    const float* __restrict__ bias, __half* __restrict__ agg,
    float* __restrict__ sums) {
    const int t = threadIdx.x;           // 0..127
    const int ch = t * 2;
    const unsigned char* __restrict__ hwb = (const unsigned char*)hw + ch * 2;
    const float2 bia = *(const float2*)(bias + ch);
    float s0a = 0.f, s1a = 0.f, q0 = 0.f, q1 = 0.f;
    __shared__ int se[2][256];

    {
        int v0 = blockIdx.x;
        if (v0 < NN) {
            int e0 = rowptr[v0];
            int n = min(256, rowptr[v0 + 1] - e0);
            if (t < n) se[0][t] = csr[e0 + t];
            if (t + 128 < n) se[0][t + 128] = csr[e0 + t + 128];
        }
    }
    int p = 0;
    for (int v = blockIdx.x; v < NN; v += gridDim.x) {
        __syncthreads();
        int vn = v + gridDim.x;
        if (vn < NN) {
            int e0n = rowptr[vn];
            int nn = min(256, rowptr[vn + 1] - e0n);
            if (t < nn) se[p ^ 1][t] = csr[e0n + t];
            if (t + 128 < nn) se[p ^ 1][t + 128] = csr[e0n + t + 128];
        }
        const float dv = dinv[v];
        float a0, a1;
        {
            float2 f = __half22float2(*(const __half2*)(hw + (size_t)v * HH + ch));
            a0 = f.x; a1 = f.y;
        }
        const int e0 = rowptr[v], e1 = rowptr[v + 1];
        const int n = min(256, e1 - e0);
        int j = 0;
        for (; j + 8 <= n; j += 8) {
            int b0 = se[p][j + 0], b1 = se[p][j + 1];
            int b2 = se[p][j + 2], b3 = se[p][j + 3];
            int b4 = se[p][j + 4], b5 = se[p][j + 5];
            int b6 = se[p][j + 6], b7 = se[p][j + 7];
            __half2 g0 = *(const __half2*)(hwb + b0);
            __half2 g1 = *(const __half2*)(hwb + b1);
            __half2 g2 = *(const __half2*)(hwb + b2);
            __half2 g3 = *(const __half2*)(hwb + b3);
            __half2 g4 = *(const __half2*)(hwb + b4);
            __half2 g5 = *(const __half2*)(hwb + b5);
            __half2 g6 = *(const __half2*)(hwb + b6);
            __half2 g7 = *(const __half2*)(hwb + b7);
            // fp16 pairwise tree (depth 3), then one fp32 accumulate
            __half2 t01 = __hadd2(g0, g1);
            __half2 t23 = __hadd2(g2, g3);
            __half2 t45 = __hadd2(g4, g5);
            __half2 t67 = __hadd2(g6, g7);
            __half2 s8 = __hadd2(__hadd2(t01, t23), __hadd2(t45, t67));
            float2 f = __half22float2(s8);
            a0 += f.x;
            a1 += f.y;
        }
        for (; j < n; j++) {
            float2 g = __half22float2(*(const __half2*)(hwb + se[p][j]));
            a0 += g.x;
            a1 += g.y;
        }
        for (int base = e0 + 256; base < e1; base += 256) {
            __syncthreads();
            int n2 = min(256, e1 - base);
            if (t < n2) se[p][t] = csr[base + t];
            if (t + 128 < n2) se[p][t + 128] = csr[base + t + 128];
            __syncthreads();
            for (int jj = 0; jj < n2; jj++) {
                float2 g = __half22float2(*(const __half2*)(hwb + se[p][jj]));
                a0 += g.x;
                a1 += g.y;
            }
        }
        p ^= 1;
        a0 = a0 * dv + bia.x;
        a1 = a1 * dv + bia.y;
        *(__half2*)(agg + (size_t)v * HH + ch) = __floats2half2_rn(a0, a1);
        s0a += a0; s1a += a1;
        q0 += a0 * a0; q1 += a1 * a1;
    }
    atomicAdd(&sums[ch + 0], s0a);
    atomicAdd(&sums[ch + 1], s1a);
    atomicAdd(&sums[HH + ch + 0], q0);
    atomicAdd(&sums[HH + ch + 1], q1);
}

// ---------------- pooling (fused final BN) + MLP -----------------------------
__global__ void k_pool(const __half* __restrict__ agg, const __half* __restrict__ hres,
                       const float* __restrict__ sums, const float* __restrict__ bn_g,
                       const float* __restrict__ bn_b, const int* __restrict__ goff,
                       float* __restrict__ pooled) {
    const int gidx = blockIdx.x;
    const int c = threadIdx.x;
    const float inv_n = 1.0f / (float)NN;
    const float mu = sums[c] * inv_n;
    const float var = sums[HH + c] * inv_n - mu * mu;
    const float rg = rsqrtf(var + 1e-5f) * bn_g[c];
    const float bb = bn_b[c];
    const int s = goff[gidx], e = goff[gidx + 1];
    float acc = 0.f;
    for (int r = s; r < e; r++) {
        float val = fmaxf((__half2float(agg[(size_t)r * HH + c]) - mu) * rg + bb, 0.f)
                  + __half2float(hres[(size_t)r * HH + c]);
        acc += val;
    }
    float cnt = (float)(e - s);
    pooled[gidx * HH + c] = acc / fmaxf(cnt, 1.0f);
}

__global__ void k_mlp(const float* __restrict__ pooled,
                      const float* __restrict__ W1, const float* __restrict__ b1,
                      const float* __restrict__ W2, const float* __restrict__ b2,
                      float* __restrict__ out) {
    const int gidx = blockIdx.x;
    const int t = threadIdx.x;  // 128
    __shared__ float sp[HH];
    __shared__ float red[128];
    sp[t] = pooled[gidx * HH + t];
    sp[t + 128] = pooled[gidx * HH + t + 128];
    __syncthreads();
    float acc = b1[t];
    #pragma unroll 8
    for (int k = 0; k < HH; k++) acc += sp[k] * W1[k * 128 + t];
    acc = fmaxf(acc, 0.f);
    red[t] = acc * W2[t];
    __syncthreads();
    for (int off = 64; off > 0; off >>= 1) {
        if (t < off) red[t] += red[t + off];
        __syncthreads();
    }
    if (t == 0) out[gidx] = red[0] + b2[0];
}

// ---------------- launch ----------------------------------------------------
extern "C" void kernel_launch(void* const* d_in, const int* in_sizes, int n_in,
                              void* d_out, int out_size) {
    const int*   x        = (const int*)d_in[0];
    const int*   tags     = (const int*)d_in[1];
    const int*   eidx     = (const int*)d_in[2];
    const int*   batch    = (const int*)d_in[3];
    const float* atom_emb = (const float*)d_in[4];
    const float* tag_emb  = (const float*)d_in[5];
    const float* Wp       = (const float*)d_in[6];
    const float* bp       = (const float*)d_in[7];
    const float* gcn_W    = (const float*)d_in[8];
    const float* gcn_b    = (const float*)d_in[9];
    const float* bn_g     = (const float*)d_in[10];
    const float* bn_b     = (const float*)d_in[11];
    const float* W1       = (const float*)d_in[12];
    const float* b1       = (const float*)d_in[13];
    const float* W2       = (const float*)d_in[14];
    const float* b2       = (const float*)d_in[15];
    float* out = (float*)d_out;

    const int* src = eidx;
    const int* dst = eidx + EE;

    float *dinv, *P, *Q, *sums, *pooled;
    __half *hA, *hD, *hwh, *aggh;
    int *cnt, *cnt2, *rowptr, *csr, *gcnt, *goff;
    unsigned char* Wimg;
    cudaGetSymbolAddress((void**)&hA, g_hA);
    cudaGetSymbolAddress((void**)&hD, g_hD);
    cudaGetSymbolAddress((void**)&hwh, g_hwh);
    cudaGetSymbolAddress((void**)&aggh, g_aggh);
    cudaGetSymbolAddress((void**)&cnt, g_cnt);
    cudaGetSymbolAddress((void**)&cnt2, g_cnt2);
    cudaGetSymbolAddress((void**)&rowptr, g_rowptr);
    cudaGetSymbolAddress((void**)&csr, g_csr);
    cudaGetSymbolAddress((void**)&gcnt, g_gcnt);
    cudaGetSymbolAddress((void**)&goff, g_goff);
    cudaGetSymbolAddress((void**)&dinv, g_dinv);
    cudaGetSymbolAddress((void**)&P, g_P);
    cudaGetSymbolAddress((void**)&Q, g_Q);
    cudaGetSymbolAddress((void**)&sums, g_sums);
    cudaGetSymbolAddress((void**)&pooled, g_pooled);
    cudaGetSymbolAddress((void**)&Wimg, g_Wimg);

    cudaFuncSetAttribute(k_gemm_mma, cudaFuncAttributeMaxDynamicSharedMemorySize, SM_GEMM);

    const int TB = 256;
    const int AGG_GRID = 4096;

    cudaMemsetAsync(cnt, 0, NN * sizeof(int));
    cudaMemsetAsync(cnt2, 0, NN * sizeof(int));
    cudaMemsetAsync(gcnt, 0, GG * sizeof(int));
    cudaMemsetAsync(sums, 0, LL * 2 * HH * sizeof(float));

    // launch 0: counting + weight images + projection tables
    k_count_weights<<<3125 + 1024 + 103, TB>>>(dst, batch, cnt, gcnt,
                                               gcn_W, Wimg, atom_emb, tag_emb, Wp, bp, P, Q);
    // launch 1: scans
    k_scan<<<1, 1024>>>(cnt, rowptr, dinv, gcnt, goff);
    // launch 2: GEMM0 (embed-fused) + fused fill_csr in extra blocks
    {
        dim3 g0(2, GY_GEMM + 1563);
        k_gemm_mma<<<g0, 256, SM_GEMM>>>(nullptr, nullptr, nullptr, nullptr, nullptr,
            Wimg, hwh, NN, P, Q, x, tags, 1, hA,
            src, dst, rowptr, dinv, cnt2, csr);
    }
    // launch 3: aggregate (PROFILED)
    k_aggregate<<<AGG_GRID, 128>>>(hwh, dinv, rowptr, csr, gcn_b, aggh, sums);

    __half* hres = hA;
    __half* hnew = hD;
    dim3 ggrid(2, GY_GEMM);
    for (int l = 1; l < LL; l++) {
        k_gemm_mma<<<ggrid, 256, SM_GEMM>>>(
            aggh, hres, sums + (size_t)(l - 1) * 2 * HH,
            bn_g + (size_t)(l - 1) * HH, bn_b + (size_t)(l - 1) * HH,
            Wimg + (size_t)l * 8 * 32768, hwh, NN, P, Q, x, tags, 2, hnew,
            src, dst, rowptr, dinv, cnt2, csr);
        k_aggregate<<<AGG_GRID, 128>>>(hwh, dinv, rowptr, csr,
                                       gcn_b + (size_t)l * HH, aggh,
                                       sums + (size_t)l * 2 * HH);
        __half* tmp = hres; hres = hnew; hnew = tmp;
    }

    k_pool<<<GG, HH>>>(aggh, hres, sums + (size_t)(LL - 1) * 2 * HH,
                       bn_g + (size_t)(LL - 1) * HH, bn_b + (size_t)(LL - 1) * HH,
                       goff, pooled);
    k_mlp<<<GG, 128>>>(pooled, W1, b1, W2, b2, out);
    (void)in_sizes; (void)n_in; (void)out_size;
}

// round 17
// speedup vs baseline: 1.0362x; 1.0362x over previous
#include <cuda_runtime.h>
#include <cuda_fp16.h>
#include <math.h>
#include <stdint.h>

#define NN 50000
#define EE 800000
#define GG 512
#define HH 256
#define TT 32
#define LL 4

// ---------------- scratch (device globals) -----------------------------------
__device__ __half g_hA[NN * HH];            // residual h buffer A (fp16)
__device__ __half g_hD[NN * HH];            // residual h buffer D (fp16)
__device__ __half g_hwh[NN * HH];           // GEMM output hw' = hw*dinv (fp16)
__device__ __half g_aggh[NN * HH];          // aggregate output (fp16)
__device__ int   g_cnt[NN];
__device__ int   g_cnt2[NN];
__device__ int   g_rowptr[NN + 1];
__device__ int   g_csr[EE];                 // src BYTE offsets (src*512)
__device__ int   g_gcnt[GG];
__device__ int   g_goff[GG + 1];
__device__ float g_dinv[NN];
__device__ float g_P[100 * HH];
__device__ float g_Q[3 * HH];
__device__ float g_sums[LL * 2 * HH];
__device__ float g_pooled[GG * HH];
// fp16 hi/lo images of W^T: [L][kc=4][split=2][32768B] = 1MB
__device__ unsigned char g_Wimg[LL * 4 * 2 * 32768];

// ---------------- helpers ----------------------------------------------------
__device__ __forceinline__ uint32_t smem_u32(const void* p) {
    uint32_t a;
    asm("{ .reg .u64 t; cvta.to.shared.u64 t, %1; cvt.u32.u64 %0, t; }" : "=r"(a) : "l"(p));
    return a;
}
__device__ __forceinline__ uint32_t swz128(uint32_t o) { return o ^ ((o >> 3) & 0x70); }

__device__ __forceinline__ void ldsm4(uint32_t* r, uint32_t addr) {
    asm volatile("ldmatrix.sync.aligned.m8n8.x4.shared.b16 {%0,%1,%2,%3}, [%4];"
        : "=r"(r[0]), "=r"(r[1]), "=r"(r[2]), "=r"(r[3]) : "r"(addr));
}
__device__ __forceinline__ void mma_f16(float* d, const uint32_t* a, const uint32_t* b) {
    asm volatile("mma.sync.aligned.m16n8k16.row.col.f32.f16.f16.f32 "
        "{%0,%1,%2,%3}, {%4,%5,%6,%7}, {%8,%9}, {%0,%1,%2,%3};"
        : "+f"(d[0]), "+f"(d[1]), "+f"(d[2]), "+f"(d[3])
        : "r"(a[0]), "r"(a[1]), "r"(a[2]), "r"(a[3]), "r"(b[0]), "r"(b[1]));
}
__device__ __forceinline__ uint32_t cvt_f16x2(float lo, float hi) {
    uint32_t r;
    asm("cvt.rn.f16x2.f32 %0, %1, %2;" : "=r"(r) : "f"(hi), "f"(lo));
    return r;
}
#define CP_ASYNC16(sa, gp) \
    asm volatile("cp.async.cg.shared.global [%0], [%1], 16;" :: "r"(sa), "l"(gp) : "memory")
#define CP_COMMIT() asm volatile("cp.async.commit_group;" ::: "memory")
#define CP_WAIT0()  asm volatile("cp.async.wait_group 0;" ::: "memory")

// ---------------- fused: counting + W fp16-hi/lo images + proj tables --------
__global__ void k_count_weights(const int* __restrict__ dst, const int* __restrict__ batch,
                                int* cnt, int* gcnt,
                                const float* __restrict__ gcn_W, unsigned char* __restrict__ img,
                                const float* __restrict__ atom_emb,
                                const float* __restrict__ tag_emb,
                                const float* __restrict__ Wp, const float* __restrict__ bp,
                                float* P, float* Q) {
    int bid = blockIdx.x;
    int tid = threadIdx.x;
    if (bid < 3125) {
        int e = bid * 256 + tid;
        if (e < EE) atomicAdd(&cnt[dst[e]], 1);
        if (e < NN) atomicAdd(&gcnt[batch[e]], 1);
    } else if (bid < 3125 + 1024) {
        int idx = (bid - 3125) * 256 + tid;
        int l = idx >> 16;
        int k = (idx >> 8) & 255;
        int n = idx & 255;
        float w = gcn_W[idx];
        __half hi = __float2half(w);
        __half lo = __float2half(w - __half2float(hi));
        int kc = k >> 6, kk = k & 63;
        uint32_t off = swz128((uint32_t)(n * 128 + kk * 2));
        size_t base = ((size_t)(l * 4 + kc) * 2) * 32768;
        *(__half*)(img + base + off) = hi;
        *(__half*)(img + base + 32768 + off) = lo;
    } else {
        int r = bid - 3125 - 1024;
        int c = tid;
        if (r < 100) {
            float acc = 0.f;
            #pragma unroll 8
            for (int k = 0; k < HH; k++) acc += atom_emb[r * HH + k] * Wp[k * HH + c];
            P[r * HH + c] = acc;
        } else {
            int t = r - 100;
            if (t < 3) {
                float acc = bp[c];
                #pragma unroll
                for (int k = 0; k < TT; k++) acc += tag_emb[t * TT + k] * Wp[(HH + k) * HH + c];
                Q[t * HH + c] = acc;
            }
        }
    }
}

__global__ __launch_bounds__(1024) void k_scan(const int* __restrict__ cnt, int* rowptr,
                                               float* dinv, const int* __restrict__ gcnt,
                                               int* goff) {
    __shared__ int wsum[32];
    const int tid = threadIdx.x;
    const int lane = tid & 31;
    const int w = tid >> 5;
    const int CH = (NN + 1023) / 1024;
    const int beg = tid * CH;
    const int end = min(beg + CH, NN);

    int tot = 0;
    for (int i = beg; i < end; i++) tot += cnt[i];
    int x = tot;
    #pragma unroll
    for (int o = 1; o < 32; o <<= 1) {
        int t = __shfl_up_sync(0xFFFFFFFFu, x, o);
        if (lane >= o) x += t;
    }
    if (lane == 31) wsum[w] = x;
    __syncthreads();
    if (w == 0) {
        int y = wsum[lane];
        #pragma unroll
        for (int o = 1; o < 32; o <<= 1) {
            int t = __shfl_up_sync(0xFFFFFFFFu, y, o);
            if (lane >= o) y += t;
        }
        wsum[lane] = y;
    }
    __syncthreads();
    int run = ((w > 0) ? wsum[w - 1] : 0) + x - tot;
    if (tid == 0) rowptr[0] = 0;
    for (int i = beg; i < end; i++) {
        int cv = cnt[i];
        dinv[i] = rsqrtf((float)cv + 1.0f);
        run += cv;
        rowptr[i + 1] = run;
    }
    __syncthreads();
    int vv = (tid < GG) ? gcnt[tid] : 0;
    int xg = vv;
    #pragma unroll
    for (int o = 1; o < 32; o <<= 1) {
        int t = __shfl_up_sync(0xFFFFFFFFu, xg, o);
        if (lane >= o) xg += t;
    }
    if (lane == 31) wsum[w] = xg;
    __syncthreads();
    if (w == 0) {
        int y = wsum[lane];
        #pragma unroll
        for (int o = 1; o < 32; o <<= 1) {
            int t = __shfl_up_sync(0xFFFFFFFFu, y, o);
            if (lane >= o) y += t;
        }
        wsum[lane] = y;
    }
    __syncthreads();
    int incl = ((w > 0) ? wsum[w - 1] : 0) + xg;
    if (tid == 0) goff[0] = 0;
    if (tid < GG) goff[tid + 1] = incl;
}

// ---------------- HMMA fp16 GEMM (A single fp16, W hi/lo fp16) ---------------
#define SM_A  0
#define SM_BH 16384
#define SM_BL 32768
#define SM_GEMM 49152
#define GY_GEMM 391

__global__ __launch_bounds__(256, 2) void k_gemm_mma(
    const __half* __restrict__ aggA, const __half* __restrict__ hres,
    const float* __restrict__ sums, const float* __restrict__ bn_g,
    const float* __restrict__ bn_b,
    const unsigned char* __restrict__ WimgL,
    __half* __restrict__ C, int M,
    const float* __restrict__ P, const float* __restrict__ Q,
    const int* __restrict__ x, const int* __restrict__ tags,
    int mode, __half* __restrict__ Aout,
    const int* __restrict__ esrc, const int* __restrict__ edst,
    const int* __restrict__ rowptr, const float* __restrict__ dinv,
    int* cnt2, int* csr) {
    extern __shared__ char smem[];
    const int tid = threadIdx.x;

    if (blockIdx.y >= GY_GEMM) {                 // fused fill_csr blocks
        int e = ((blockIdx.y - GY_GEMM) * 2 + blockIdx.x) * 256 + tid;
        if (e < EE) {
            int s = esrc[e], d = edst[e];
            int pos = rowptr[d] + atomicAdd(&cnt2[d], 1);
            csr[pos] = s * (HH * 2);             // byte offset of row
        }
        return;
    }

    const int wid = tid >> 5;
    const int lane = tid & 31;
    const int wm = wid & 3;
    const int wn = wid >> 2;
    const uint32_t sb = smem_u32(smem);
    const int bm = blockIdx.y * 128;
    const int bn = blockIdx.x * 128;
    const int c4 = (tid & 15) << 2;
    const bool do_write_a = (blockIdx.x == 0);

    float acc[2][8][4];
    #pragma unroll
    for (int mi = 0; mi < 2; mi++)
        #pragma unroll
        for (int j = 0; j < 8; j++)
            #pragma unroll
            for (int q = 0; q < 4; q++) acc[mi][j][q] = 0.f;

    const float inv_n = 1.0f / (float)NN;

    for (int kc = 0; kc < 4; kc++) {
        // ---- B tiles via cp.async FIRST (overlaps with A prologue below)
        {
            const unsigned char* srcH = WimgL + (size_t)kc * 65536 + (size_t)bn * 128;
            const unsigned char* srcL = srcH + 32768;
            #pragma unroll
            for (int i = 0; i < 4; i++) {
                uint32_t o = (uint32_t)(tid + i * 256) * 16;
                CP_ASYNC16(sb + SM_BH + o, srcH + o);
                CP_ASYNC16(sb + SM_BL + o, srcL + o);
            }
            CP_COMMIT();
        }
        const int col = kc * 64 + c4;
        float mu0 = 0.f, mu1 = 0.f, mu2 = 0.f, mu3 = 0.f;
        float rg0 = 0.f, rg1 = 0.f, rg2 = 0.f, rg3 = 0.f;
        float bb0 = 0.f, bb1 = 0.f, bb2 = 0.f, bb3 = 0.f;
        if (mode == 2) {
            mu0 = sums[col + 0] * inv_n;
            mu1 = sums[col + 1] * inv_n;
            mu2 = sums[col + 2] * inv_n;
            mu3 = sums[col + 3] * inv_n;
            float v0 = sums[HH + col + 0] * inv_n - mu0 * mu0;
            float v1 = sums[HH + col + 1] * inv_n - mu1 * mu1;
            float v2 = sums[HH + col + 2] * inv_n - mu2 * mu2;
            float v3 = sums[HH + col + 3] * inv_n - mu3 * mu3;
            rg0 = rsqrtf(v0 + 1e-5f) * bn_g[col + 0];
            rg1 = rsqrtf(v1 + 1e-5f) * bn_g[col + 1];
            rg2 = rsqrtf(v2 + 1e-5f) * bn_g[col + 2];
            rg3 = rsqrtf(v3 + 1e-5f) * bn_g[col + 3];
            bb0 = bn_b[col + 0];
            bb1 = bn_b[col + 1];
            bb2 = bn_b[col + 2];
            bb3 = bn_b[col + 3];
        }
        #pragma unroll
        for (int i = 0; i < 8; i++) {
            int r = (tid >> 4) + i * 16;
            int gr = bm + r;
            float4 v = make_float4(0.f, 0.f, 0.f, 0.f);
            if (gr < M) {
                if (mode == 1) {
                    int xi = x[gr], tg = tags[gr];
                    float4 p = *(const float4*)(P + (size_t)xi * HH + col);
                    float4 q = *(const float4*)(Q + (size_t)tg * HH + col);
                    v = make_float4(p.x + q.x, p.y + q.y, p.z + q.z, p.w + q.w);
                } else {
                    uint2 au = *(const uint2*)(aggA + (size_t)gr * HH + col);
                    uint2 ru = *(const uint2*)(hres + (size_t)gr * HH + col);
                    float2 a01 = __half22float2(*(const __half2*)&au.x);
                    float2 a23 = __half22float2(*(const __half2*)&au.y);
                    float2 r01 = __half22float2(*(const __half2*)&ru.x);
                    float2 r23 = __half22float2(*(const __half2*)&ru.y);
                    v.x = fmaxf((a01.x - mu0) * rg0 + bb0, 0.f) + r01.x;
                    v.y = fmaxf((a01.y - mu1) * rg1 + bb1, 0.f) + r01.y;
                    v.z = fmaxf((a23.x - mu2) * rg2 + bb2, 0.f) + r23.x;
                    v.w = fmaxf((a23.y - mu3) * rg3 + bb3, 0.f) + r23.y;
                }
            }
            uint2 hv = make_uint2(cvt_f16x2(v.x, v.y), cvt_f16x2(v.z, v.w));
            if (gr < M && do_write_a)
                *(uint2*)(Aout + (size_t)gr * HH + col) = hv;
            uint32_t off = swz128((uint32_t)(r * 128 + c4 * 2));
            *(uint2*)(smem + SM_A + off) = hv;
        }
        CP_WAIT0();
        __syncthreads();

        #pragma unroll
        for (int ks = 0; ks < 4; ks++) {
            uint32_t ah[2][4];
            {
                int rowa = 32 * wm + (lane & 15);
                int kb = ks * 32 + ((lane >> 4) << 4);
                uint32_t off0 = swz128((uint32_t)(rowa * 128 + kb));
                uint32_t off1 = swz128((uint32_t)((rowa + 16) * 128 + kb));
                ldsm4(ah[0], sb + SM_A + off0);
                ldsm4(ah[1], sb + SM_A + off1);
            }
            #pragma unroll
            for (int jp = 0; jp < 4; jp++) {
                int n0 = 64 * wn + 16 * jp;
                int nrow = n0 + ((lane >> 4) << 3) + (lane & 7);
                int kb2 = ks * 32 + (((lane >> 3) & 1) << 4);
                uint32_t offb = swz128((uint32_t)(nrow * 128 + kb2));
                uint32_t bh[4], bl[4];
                ldsm4(bh, sb + SM_BH + offb);
                ldsm4(bl, sb + SM_BL + offb);
                #pragma unroll
                for (int mi = 0; mi < 2; mi++) {
                    #pragma unroll
                    for (int jq = 0; jq < 2; jq++) {
                        float* d = acc[mi][jp * 2 + jq];
                        mma_f16(d, ah[mi], bh + 2 * jq);
                        mma_f16(d, ah[mi], bl + 2 * jq);
                    }
                }
            }
        }
        __syncthreads();
    }

    // epilogue: fold dinv[row] into C (hw' = hw * dinv)
    #pragma unroll
    for (int mi = 0; mi < 2; mi++) {
        int r0 = bm + 32 * wm + 16 * mi + (lane >> 2);
        int r1 = r0 + 8;
        float di0 = (r0 < M) ? dinv[r0] : 0.f;
        float di1 = (r1 < M) ? dinv[r1] : 0.f;
        #pragma unroll
        for (int j = 0; j < 8; j++) {
            int c = bn + 64 * wn + 8 * j + (lane & 3) * 2;
            if (r0 < M)
                *(__half2*)(C + (size_t)r0 * HH + c) =
                    __floats2half2_rn(acc[mi][j][0] * di0, acc[mi][j][1] * di0);
            if (r1 < M)
                *(__half2*)(C + (size_t)r1 * HH + c) =
                    __floats2half2_rn(acc[mi][j][2] * di1, acc[mi][j][3] * di1);
        }
    }
}

// ---------------- aggregation: R15 loop + byte-offset CSR --------------------
// agg[v] = dinv[v]*(sum_src hw'[src] + hw'[v]) + bias,  hw' = hw*dinv prefolded.
__global__ __launch_bounds__(128) void k_aggregate(
    const __half* __restrict__ hw, const float* __restrict__ dinv,
    const int* __restrict__ rowptr, const int* __restrict__ csr,
    const float* __restrict__ bias, __half* __restrict__ agg,
    float* __restrict__ sums) {
    const int t = threadIdx.x;           // 0..127
    const int ch = t * 2;
    const unsigned char* __restrict__ hwb = (const unsigned char*)hw + ch * 2;
    const float2 bia = *(const float2*)(bias + ch);
    float s0a = 0.f, s1a = 0.f, q0 = 0.f, q1 = 0.f;
    __shared__ int se[2][256];

    {
        int v0 = blockIdx.x;
        if (v0 < NN) {
            int e0 = rowptr[v0];
            int n = min(256, rowptr[v0 + 1] - e0);
            if (t < n) se[0][t] = csr[e0 + t];
            if (t + 128 < n) se[0][t + 128] = csr[e0 + t + 128];
        }
    }
    int p = 0;
    for (int v = blockIdx.x; v < NN; v += gridDim.x) {
        __syncthreads();
        int vn = v + gridDim.x;
        if (vn < NN) {
            int e0n = rowptr[vn];
            int nn = min(256, rowptr[vn + 1] - e0n);
            if (t < nn) se[p ^ 1][t] = csr[e0n + t];
            if (t + 128 < nn) se[p ^ 1][t + 128] = csr[e0n + t + 128];
        }
        const float dv = dinv[v];
        float a0, a1;
        {
            float2 f = __half22float2(*(const __half2*)(hw + (size_t)v * HH + ch));
            a0 = f.x; a1 = f.y;
        }
        const int e0 = rowptr[v], e1 = rowptr[v + 1];
        const int n = min(256, e1 - e0);
        int j = 0;
        for (; j + 8 <= n; j += 8) {
            int b0 = se[p][j + 0], b1 = se[p][j + 1];
            int b2 = se[p][j + 2], b3 = se[p][j + 3];
            int b4 = se[p][j + 4], b5 = se[p][j + 5];
            int b6 = se[p][j + 6], b7 = se[p][j + 7];
            __half2 g0 = *(const __half2*)(hwb + b0);
            __half2 g1 = *(const __half2*)(hwb + b1);
            __half2 g2 = *(const __half2*)(hwb + b2);
            __half2 g3 = *(const __half2*)(hwb + b3);
            __half2 g4 = *(const __half2*)(hwb + b4);
            __half2 g5 = *(const __half2*)(hwb + b5);
            __half2 g6 = *(const __half2*)(hwb + b6);
            __half2 g7 = *(const __half2*)(hwb + b7);
            float2 f0 = __half22float2(g0), f1 = __half22float2(g1);
            float2 f2 = __half22float2(g2), f3 = __half22float2(g3);
            float2 f4 = __half22float2(g4), f5 = __half22float2(g5);
            float2 f6 = __half22float2(g6), f7 = __half22float2(g7);
            a0 += f0.x + f1.x + f2.x + f3.x + f4.x + f5.x + f6.x + f7.x;
            a1 += f0.y + f1.y + f2.y + f3.y + f4.y + f5.y + f6.y + f7.y;
        }
        for (; j < n; j++) {
            float2 g = __half22float2(*(const __half2*)(hwb + se[p][j]));
            a0 += g.x;
            a1 += g.y;
        }
        for (int base = e0 + 256; base < e1; base += 256) {
            __syncthreads();
            int n2 = min(256, e1 - base);
            if (t < n2) se[p][t] = csr[base + t];
            if (t + 128 < n2) se[p][t + 128] = csr[base + t + 128];
            __syncthreads();
            for (int jj = 0; jj < n2; jj++) {
                float2 g = __half22float2(*(const __half2*)(hwb + se[p][jj]));
                a0 += g.x;
                a1 += g.y;
            }
        }
        p ^= 1;
        a0 = a0 * dv + bia.x;
        a1 = a1 * dv + bia.y;
        *(__half2*)(agg + (size_t)v * HH + ch) = __floats2half2_rn(a0, a1);
        s0a += a0; s1a += a1;
        q0 += a0 * a0; q1 += a1 * a1;
    }
    atomicAdd(&sums[ch + 0], s0a);
    atomicAdd(&sums[ch + 1], s1a);
    atomicAdd(&sums[HH + ch + 0], q0);
    atomicAdd(&sums[HH + ch + 1], q1);
}

// ---------------- pooling (fused final BN) + MLP -----------------------------
__global__ void k_pool(const __half* __restrict__ agg, const __half* __restrict__ hres,
                       const float* __restrict__ sums, const float* __restrict__ bn_g,
                       const float* __restrict__ bn_b, const int* __restrict__ goff,
                       float* __restrict__ pooled) {
    const int gidx = blockIdx.x;
    const int c = threadIdx.x;
    const float inv_n = 1.0f / (float)NN;
    const float mu = sums[c] * inv_n;
    const float var = sums[HH + c] * inv_n - mu * mu;
    const float rg = rsqrtf(var + 1e-5f) * bn_g[c];
    const float bb = bn_b[c];
    const int s = goff[gidx], e = goff[gidx + 1];
    float acc = 0.f;
    for (int r = s; r < e; r++) {
        float val = fmaxf((__half2float(agg[(size_t)r * HH + c]) - mu) * rg + bb, 0.f)
                  + __half2float(hres[(size_t)r * HH + c]);
        acc += val;
    }
    float cnt = (float)(e - s);
    pooled[gidx * HH + c] = acc / fmaxf(cnt, 1.0f);
}

__global__ void k_mlp(const float* __restrict__ pooled,
                      const float* __restrict__ W1, const float* __restrict__ b1,
                      const float* __restrict__ W2, const float* __restrict__ b2,
                      float* __restrict__ out) {
    const int gidx = blockIdx.x;
    const int t = threadIdx.x;  // 128
    __shared__ float sp[HH];
    __shared__ float red[128];
    sp[t] = pooled[gidx * HH + t];
    sp[t + 128] = pooled[gidx * HH + t + 128];
    __syncthreads();
    float acc = b1[t];
    #pragma unroll 8
    for (int k = 0; k < HH; k++) acc += sp[k] * W1[k * 128 + t];
    acc = fmaxf(acc, 0.f);
    red[t] = acc * W2[t];
    __syncthreads();
    for (int off = 64; off > 0; off >>= 1) {
        if (t < off) red[t] += red[t + off];
        __syncthreads();
    }
    if (t == 0) out[gidx] = red[0] + b2[0];
}

// ---------------- launch ----------------------------------------------------
extern "C" void kernel_launch(void* const* d_in, const int* in_sizes, int n_in,
                              void* d_out, int out_size) {
    const int*   x        = (const int*)d_in[0];
    const int*   tags     = (const int*)d_in[1];
    const int*   eidx     = (const int*)d_in[2];
    const int*   batch    = (const int*)d_in[3];
    const float* atom_emb = (const float*)d_in[4];
    const float* tag_emb  = (const float*)d_in[5];
    const float* Wp       = (const float*)d_in[6];
    const float* bp       = (const float*)d_in[7];
    const float* gcn_W    = (const float*)d_in[8];
    const float* gcn_b    = (const float*)d_in[9];
    const float* bn_g     = (const float*)d_in[10];
    const float* bn_b     = (const float*)d_in[11];
    const float* W1       = (const float*)d_in[12];
    const float* b1       = (const float*)d_in[13];
    const float* W2       = (const float*)d_in[14];
    const float* b2       = (const float*)d_in[15];
    float* out = (float*)d_out;

    const int* src = eidx;
    const int* dst = eidx + EE;

    float *dinv, *P, *Q, *sums, *pooled;
    __half *hA, *hD, *hwh, *aggh;
    int *cnt, *cnt2, *rowptr, *csr, *gcnt, *goff;
    unsigned char* Wimg;
    cudaGetSymbolAddress((void**)&hA, g_hA);
    cudaGetSymbolAddress((void**)&hD, g_hD);
    cudaGetSymbolAddress((void**)&hwh, g_hwh);
    cudaGetSymbolAddress((void**)&aggh, g_aggh);
    cudaGetSymbolAddress((void**)&cnt, g_cnt);
    cudaGetSymbolAddress((void**)&cnt2, g_cnt2);
    cudaGetSymbolAddress((void**)&rowptr, g_rowptr);
    cudaGetSymbolAddress((void**)&csr, g_csr);
    cudaGetSymbolAddress((void**)&gcnt, g_gcnt);
    cudaGetSymbolAddress((void**)&goff, g_goff);
    cudaGetSymbolAddress((void**)&dinv, g_dinv);
    cudaGetSymbolAddress((void**)&P, g_P);
    cudaGetSymbolAddress((void**)&Q, g_Q);
    cudaGetSymbolAddress((void**)&sums, g_sums);
    cudaGetSymbolAddress((void**)&pooled, g_pooled);
    cudaGetSymbolAddress((void**)&Wimg, g_Wimg);

    cudaFuncSetAttribute(k_gemm_mma, cudaFuncAttributeMaxDynamicSharedMemorySize, SM_GEMM);

    const int TB = 256;
    const int AGG_GRID = 4096;

    cudaMemsetAsync(cnt, 0, NN * sizeof(int));
    cudaMemsetAsync(cnt2, 0, NN * sizeof(int));
    cudaMemsetAsync(gcnt, 0, GG * sizeof(int));
    cudaMemsetAsync(sums, 0, LL * 2 * HH * sizeof(float));

    // launch 0: counting + weight images + projection tables
    k_count_weights<<<3125 + 1024 + 103, TB>>>(dst, batch, cnt, gcnt,
                                               gcn_W, Wimg, atom_emb, tag_emb, Wp, bp, P, Q);
    // launch 1: scans
    k_scan<<<1, 1024>>>(cnt, rowptr, dinv, gcnt, goff);
    // launch 2: GEMM0 (embed-fused) + fused fill_csr in extra blocks
    {
        dim3 g0(2, GY_GEMM + 1563);
        k_gemm_mma<<<g0, 256, SM_GEMM>>>(nullptr, nullptr, nullptr, nullptr, nullptr,
            Wimg, hwh, NN, P, Q, x, tags, 1, hA,
            src, dst, rowptr, dinv, cnt2, csr);
    }
    // launch 3: aggregate (PROFILED)
    k_aggregate<<<AGG_GRID, 128>>>(hwh, dinv, rowptr, csr, gcn_b, aggh, sums);

    __half* hres = hA;
    __half* hnew = hD;
    dim3 ggrid(2, GY_GEMM);
    for (int l = 1; l < LL; l++) {
        k_gemm_mma<<<ggrid, 256, SM_GEMM>>>(
            aggh, hres, sums + (size_t)(l - 1) * 2 * HH,
            bn_g + (size_t)(l - 1) * HH, bn_b + (size_t)(l - 1) * HH,
            Wimg + (size_t)l * 8 * 32768, hwh, NN, P, Q, x, tags, 2, hnew,
            src, dst, rowptr, dinv, cnt2, csr);
        k_aggregate<<<AGG_GRID, 128>>>(hwh, dinv, rowptr, csr,
                                       gcn_b + (size_t)l * HH, aggh,
                                       sums + (size_t)l * 2 * HH);
        __half* tmp = hres; hres = hnew; hnew = tmp;
    }

    k_pool<<<GG, HH>>>(aggh, hres, sums + (size_t)(LL - 1) * 2 * HH,
                       bn_g + (size_t)(LL - 1) * HH, bn_b + (size_t)(LL - 1) * HH,
                       goff, pooled);
    k_mlp<<<GG, 128>>>(pooled, W1, b1, W2, b2, out);
    (void)in_sizes; (void)n_in; (void)out_size;
}